// round 16
// baseline (speedup 1.0000x reference)
#include <cuda_runtime.h>
#include <cuda_fp16.h>
#include <math.h>
#include <stdint.h>

#define T_TOK 16384
#define DDIM  2048
#define DHALF 1024
#define ND    64
#define NE    3
#define LN_EPS 1e-5f
#define FIXCAP 4096

// mma.sync GEMM tiling — BM=128, BN=128, BK=64 (best measured config)
#define BM 128
#define BN 128
#define BKC 64
#define STAGE_B 32768
#define OFF_B 16384
#define GEMM_SMEM (3 * STAGE_B)  // 98304

// enc1 tiling (BN=64, BK=32)
#define E1_STAGE 12288
#define E1_OFFB 8192
#define E1_SMEM (3 * E1_STAGE)

// -------- device scratch --------
__device__ __half g_do[(size_t)T_TOK * DDIM];
__device__ float g_strength[T_TOK];
__device__ float g_hpart[(size_t)T_TOK * 48];
__device__ int   g_sel[T_TOK];
__device__ int   g_idx[T_TOK];
__device__ int   g_cnt[NE];
__device__ int   g_cur[NE];
__device__ int   g_off[NE + 1];
__device__ int   g_fix_n;
__device__ int   g_fix[FIXCAP];
__device__ float g_fixlog[FIXCAP * 12];

__device__ __half g_xh[(size_t)T_TOK * DDIM];
__device__ __half g_dhh[(size_t)(T_TOK + 256) * DDIM];
__device__ __half g_h1[(size_t)(T_TOK + 256) * ND];
__device__ __half g_nh[(size_t)(T_TOK + 256) * ND];
__device__ __half g_w1h[(size_t)DDIM * DDIM];
__device__ __half g_w2h[(size_t)NE * DDIM * DDIM];
__device__ __half g_we1t[(size_t)NE * ND * DDIM];
__device__ __half g_wd1t[(size_t)NE * DDIM * ND];
__device__ float g_b1f[DDIM];

__device__ __forceinline__ float siluf(float v) { return v / (1.f + expf(-v)); }

__device__ __forceinline__ uint32_t smem_u32(const void* p) {
    uint32_t a;
    asm("{ .reg .u64 t; cvta.to.shared.u64 t, %1; cvt.u32.u64 %0, t; }" : "=r"(a) : "l"(p));
    return a;
}
__device__ __forceinline__ void cpa16(uint32_t dst, const void* src) {
    asm volatile("cp.async.cg.shared.global [%0], [%1], 16;" :: "r"(dst), "l"(src) : "memory");
}
__device__ __forceinline__ void ldm4(uint32_t* r, uint32_t addr) {
    asm volatile("ldmatrix.sync.aligned.m8n8.x4.shared.b16 {%0,%1,%2,%3}, [%4];"
        : "=r"(r[0]), "=r"(r[1]), "=r"(r[2]), "=r"(r[3]) : "r"(addr));
}
__device__ __forceinline__ void mma16816(float* c, const uint32_t* a, uint32_t b0, uint32_t b1) {
    asm volatile("mma.sync.aligned.m16n8k16.row.col.f32.f16.f16.f32 "
        "{%0,%1,%2,%3}, {%4,%5,%6,%7}, {%8,%9}, {%0,%1,%2,%3};"
        : "+f"(c[0]), "+f"(c[1]), "+f"(c[2]), "+f"(c[3])
        : "r"(a[0]), "r"(a[1]), "r"(a[2]), "r"(a[3]), "r"(b0), "r"(b1));
}
__device__ __forceinline__ uint32_t swz(uint32_t off) { return off ^ ((off >> 3) & 0x30); }
__device__ __forceinline__ uint32_t ldm_addr(int row, int lcb) {
    return (uint32_t)(row * 64 + (lcb ^ ((row & 6) << 3)));
}

// ---------------- small kernels ----------------
// x -> fp16; block 0 also zeroes counters
__global__ void __launch_bounds__(256) split_x_kernel(const float* __restrict__ x) {
    if (blockIdx.x == 0 && threadIdx.x < 4) {
        if (threadIdx.x < NE) { g_cnt[threadIdx.x] = 0; g_cur[threadIdx.x] = 0; }
        if (threadIdx.x == 0) g_fix_n = 0;
    }
    size_t i = ((size_t)blockIdx.x * 256 + threadIdx.x) * 8;
    float4 a = *(const float4*)(x + i);
    float4 b = *(const float4*)(x + i + 4);
    __half2 h0 = __floats2half2_rn(a.x, a.y);
    __half2 h1 = __floats2half2_rn(a.z, a.w);
    __half2 h2 = __floats2half2_rn(b.x, b.y);
    __half2 h3 = __floats2half2_rn(b.z, b.w);
    uint4 o;
    o.x = *(uint32_t*)&h0; o.y = *(uint32_t*)&h1;
    o.z = *(uint32_t*)&h2; o.w = *(uint32_t*)&h3;
    *(uint4*)(g_xh + i) = o;
}

// scatter: offsets derived locally from g_cnt (final before this launch); block 0 publishes g_off
__global__ void scatter_kernel() {
    int c0 = g_cnt[0], c1 = g_cnt[1];
    if (blockIdx.x == 0 && threadIdx.x == 0) {
        g_off[0] = 0; g_off[1] = c0; g_off[2] = c0 + c1; g_off[3] = c0 + c1 + g_cnt[2];
    }
    int t = blockIdx.x * 256 + threadIdx.x;
    if (t >= T_TOK) return;
    int e = g_sel[t];
    int base = (e > 0 ? c0 : 0) + (e > 1 ? c1 : 0);
    int p = atomicAdd(&g_cur[e], 1);
    g_idx[base + p] = t;
}

// fused cls|var W1^T conversion; y==0 also writes fused bias
__global__ void __launch_bounds__(256)
conv_w1t_kernel(const float* __restrict__ cls_w1, const float* __restrict__ var_w1,
                const float* __restrict__ cls_b1, const float* __restrict__ var_b1) {
    __shared__ float tile[32][33];
    int n0 = blockIdx.x * 32, k0 = blockIdx.y * 32;
    int tx = threadIdx.x & 31, ty = threadIdx.x >> 5;
    if (blockIdx.y == 0 && ty == 0) {
        int n = n0 + tx;
        g_b1f[n] = (n < DHALF) ? cls_b1[n] : var_b1[n - DHALF];
    }
    for (int r = ty; r < 32; r += 8) {
        int k = k0 + r, n = n0 + tx;
        tile[r][tx] = (n < DHALF) ? cls_w1[(size_t)k * DHALF + n]
                                  : var_w1[(size_t)k * DHALF + n - DHALF];
    }
    __syncthreads();
    for (int r = ty; r < 32; r += 8)
        g_w1h[(size_t)(n0 + r) * DDIM + k0 + tx] = __float2half_rn(tile[tx][r]);
}

__global__ void __launch_bounds__(256)
conv_w2t_kernel(const float* __restrict__ w2) {
    __shared__ float tile[32][33];
    int e = blockIdx.z;
    int n0 = blockIdx.x * 32, k0 = blockIdx.y * 32;
    int tx = threadIdx.x & 31, ty = threadIdx.x >> 5;
    const float* src = w2 + (size_t)e * DDIM * DDIM;
    for (int r = ty; r < 32; r += 8)
        tile[r][tx] = src[(size_t)(k0 + r) * DDIM + n0 + tx];
    __syncthreads();
    __half* dh = g_w2h + (size_t)e * DDIM * DDIM;
    for (int r = ty; r < 32; r += 8)
        dh[(size_t)(n0 + r) * DDIM + k0 + tx] = __float2half_rn(tile[tx][r]);
}

__global__ void __launch_bounds__(256)
conv_we1t_kernel(const float* __restrict__ w) {
    __shared__ float tile[32][33];
    int e = blockIdx.z;
    int n0 = blockIdx.x * 32, k0 = blockIdx.y * 32;
    int tx = threadIdx.x & 31, ty = threadIdx.x >> 5;
    const float* src = w + (size_t)e * DDIM * ND;
    for (int r = ty; r < 32; r += 8)
        tile[r][tx] = src[(size_t)(k0 + r) * ND + n0 + tx];
    __syncthreads();
    __half* dst = g_we1t + (size_t)e * ND * DDIM;
    for (int r = ty; r < 32; r += 8)
        dst[(size_t)(n0 + r) * DDIM + k0 + tx] = __float2half_rn(tile[tx][r]);
}

__global__ void __launch_bounds__(256)
conv_wd1t_kernel(const float* __restrict__ w) {
    __shared__ float tile[32][33];
    int e = blockIdx.z;
    int n0 = blockIdx.x * 32, k0 = blockIdx.y * 32;
    int tx = threadIdx.x & 31, ty = threadIdx.x >> 5;
    const float* src = w + (size_t)e * ND * DDIM;
    for (int r = ty; r < 32; r += 8)
        tile[r][tx] = src[(size_t)(k0 + r) * DDIM + n0 + tx];
    __syncthreads();
    __half* dst = g_wd1t + (size_t)e * DDIM * ND;
    for (int r = ty; r < 32; r += 8)
        dst[(size_t)(n0 + r) * ND + k0 + tx] = __float2half_rn(tile[tx][r]);
}

// ---------------- mma.sync fp16 GEMM (BK=64, hoisted addressing) ----------------
template <int MODE>
__global__ void __launch_bounds__(256)
mma_gemm_kernel(const float* __restrict__ dec_b2, const float* __restrict__ dec_b1,
                const float* __restrict__ cls_w2p, const float* __restrict__ var_w2p)
{
    constexpr int KD  = (MODE == 2) ? 64 : 2048;
    constexpr int LDA = (MODE == 2) ? 64 : 2048;
    constexpr int LDB = (MODE == 2) ? 64 : 2048;
    constexpr int NCHm = KD / BKC;

    int colBase = blockIdx.x * BN;
    int rowBase, rowEnd;
    const __half *Ah, *Bh;
    const float* bp;
    if (MODE == 0) {
        rowBase = blockIdx.y * BM; rowEnd = T_TOK;
        Ah = g_xh; Bh = g_w1h; bp = g_b1f;
    } else {
        int e = blockIdx.z;
        rowEnd = g_off[e + 1];
        rowBase = g_off[e] + blockIdx.y * BM;
        if (rowBase >= rowEnd) return;
        if (MODE == 1) {
            Ah = g_dhh; Bh = g_w2h + (size_t)e * DDIM * DDIM; bp = dec_b2 + e * DDIM;
        } else {
            Ah = g_nh; Bh = g_wd1t + (size_t)e * DDIM * ND; bp = dec_b1 + e * DDIM;
        }
    }

    extern __shared__ char smem[];
    uint32_t sb = smem_u32(smem);
    int tid = threadIdx.x, lane = tid & 31, wid = tid >> 5;
    int wm = (wid & 1) * 64, wn = (wid >> 1) * 32;

    float acc[4][4][4];
    #pragma unroll
    for (int i = 0; i < 4; i++)
        #pragma unroll
        for (int j = 0; j < 4; j++)
            #pragma unroll
            for (int q = 0; q < 4; q++) acc[i][j][q] = 0.f;

    const __half* gsrc[4];
    uint32_t sdst[4];
    {
        int row0 = tid >> 2, c = tid & 3;
        int row1 = row0 + 64;
        uint32_t d0 = swz(row0 * 64 + c * 16);
        uint32_t d1 = swz(row1 * 64 + c * 16);
        sdst[0] = d0;            gsrc[0] = Ah + (size_t)(rowBase + row0) * LDA + c * 8;
        sdst[1] = d1;            gsrc[1] = Ah + (size_t)(rowBase + row1) * LDA + c * 8;
        sdst[2] = OFF_B + d0;    gsrc[2] = Bh + (size_t)(colBase + row0) * LDB + c * 8;
        sdst[3] = OFF_B + d1;    gsrc[3] = Bh + (size_t)(colBase + row1) * LDB + c * 8;
    }
    auto load_stage = [&](uint32_t stOff) {
        #pragma unroll
        for (int p = 0; p < 4; p++) {
            cpa16(sb + stOff + sdst[p], gsrc[p]);
            cpa16(sb + stOff + sdst[p] + 8192, gsrc[p] + 32);
            gsrc[p] += BKC;
        }
        asm volatile("cp.async.commit_group;" ::: "memory");
    };

    load_stage(0);
    if (NCHm > 1) load_stage(STAGE_B);

    int lr = lane & 15, lcb = (lane >> 4) << 4;
    uint32_t aAddr[4], bAddr[2];
    #pragma unroll
    for (int mt = 0; mt < 4; mt++) aAddr[mt] = ldm_addr(wm + mt * 16 + lr, lcb);
    #pragma unroll
    for (int bt = 0; bt < 2; bt++) bAddr[bt] = OFF_B + ldm_addr(wn + bt * 16 + lr, lcb);

    uint32_t stOff = 0, ldOff = 2 * STAGE_B;
    for (int ck = 0; ck < NCHm; ck++) {
        if (NCHm > 1 && ck < NCHm - 1) asm volatile("cp.async.wait_group 1;" ::: "memory");
        else                           asm volatile("cp.async.wait_group 0;" ::: "memory");
        __syncthreads();
        if (ck + 2 < NCHm) {
            load_stage(ldOff);
            ldOff += STAGE_B; if (ldOff == 3 * STAGE_B) ldOff = 0;
        }
        uint32_t st = sb + stOff;
        stOff += STAGE_B; if (stOff == 3 * STAGE_B) stOff = 0;

        #pragma unroll
        for (int ks = 0; ks < 4; ks++) {
            uint32_t base = st + ((ks >> 1) << 13);
            uint32_t kx = (ks & 1) << 5;
            uint32_t ah[4][4], bh[2][4];
            #pragma unroll
            for (int mt = 0; mt < 4; mt++) ldm4(ah[mt], base + (aAddr[mt] ^ kx));
            #pragma unroll
            for (int bt = 0; bt < 2; bt++) ldm4(bh[bt], base + (bAddr[bt] ^ kx));
            #pragma unroll
            for (int mt = 0; mt < 4; mt++)
                #pragma unroll
                for (int nt = 0; nt < 4; nt++) {
                    int bt = nt >> 1, ss = nt & 1;
                    mma16816(acc[mt][nt], ah[mt], bh[bt][ss], bh[bt][ss + 2]);
                }
        }
    }

    if (MODE == 0) {
        __syncthreads();
        float* sred = (float*)smem;
        float* w2s  = (float*)(smem + 8192);
        float* bs   = (float*)(smem + 8192 + 2048);
        bool isCls = (colBase < DHALF);
        if (isCls) {
            for (int j = tid; j < 384; j += 256) w2s[j] = cls_w2p[colBase * 3 + j];
        } else {
            for (int j = tid; j < 128; j += 256) w2s[j] = var_w2p[colBase - DHALF + j];
        }
        for (int j = tid; j < 128; j += 256) bs[j] = bp[colBase + j];
        __syncthreads();

        float ps[4][2][3];
        #pragma unroll
        for (int mt = 0; mt < 4; mt++)
            #pragma unroll
            for (int hh = 0; hh < 2; hh++)
                #pragma unroll
                for (int j = 0; j < 3; j++) ps[mt][hh][j] = 0.f;

        #pragma unroll
        for (int mt = 0; mt < 4; mt++)
            #pragma unroll
            for (int nt = 0; nt < 4; nt++) {
                int lc = wn + nt * 8 + (lane & 3) * 2;
                float b0 = bs[lc], b1 = bs[lc + 1];
                float h00 = siluf(acc[mt][nt][0] + b0);
                float h01 = siluf(acc[mt][nt][1] + b1);
                float h10 = siluf(acc[mt][nt][2] + b0);
                float h11 = siluf(acc[mt][nt][3] + b1);
                if (isCls) {
                    #pragma unroll
                    for (int j = 0; j < 3; j++) {
                        ps[mt][0][j] += h00 * w2s[lc * 3 + j] + h01 * w2s[(lc + 1) * 3 + j];
                        ps[mt][1][j] += h10 * w2s[lc * 3 + j] + h11 * w2s[(lc + 1) * 3 + j];
                    }
                } else {
                    ps[mt][0][0] += h00 * w2s[lc] + h01 * w2s[lc + 1];
                    ps[mt][1][0] += h10 * w2s[lc] + h11 * w2s[lc + 1];
                }
            }

        #pragma unroll
        for (int mt = 0; mt < 4; mt++)
            #pragma unroll
            for (int hh = 0; hh < 2; hh++)
                #pragma unroll
                for (int j = 0; j < 3; j++) {
                    float v = ps[mt][hh][j];
                    v += __shfl_xor_sync(0xffffffffu, v, 1);
                    v += __shfl_xor_sync(0xffffffffu, v, 2);
                    if ((lane & 3) == 0) {
                        int rloc = wm + mt * 16 + (lane >> 2) + hh * 8;
                        sred[((wid >> 1) * 128 + rloc) * 3 + j] = v;
                    }
                }
        __syncthreads();
        for (int idx = tid; idx < 384; idx += 256) {
            int row = idx / 3, j = idx % 3;
            float s = sred[row * 3 + j] + sred[384 + row * 3 + j]
                    + sred[768 + row * 3 + j] + sred[1152 + row * 3 + j];
            g_hpart[(size_t)(rowBase + row) * 48 + blockIdx.x * 3 + j] = s;
        }
        return;
    }

    #pragma unroll
    for (int nt = 0; nt < 4; nt++) {
        int cc = colBase + wn + nt * 8 + (lane & 3) * 2;
        float b0 = bp[cc], b1 = bp[cc + 1];
        #pragma unroll
        for (int mt = 0; mt < 4; mt++) {
            int r0 = rowBase + wm + mt * 16 + (lane >> 2);
            float* p = acc[mt][nt];
            if (MODE == 1) {
                if (r0 < rowEnd) {
                    __half2 v = __floats2half2_rn(p[0] + b0, p[1] + b1);
                    *(__half2*)(g_do + (size_t)r0 * DDIM + cc) = v;
                }
                if (r0 + 8 < rowEnd) {
                    __half2 v = __floats2half2_rn(p[2] + b0, p[3] + b1);
                    *(__half2*)(g_do + (size_t)(r0 + 8) * DDIM + cc) = v;
                }
            } else {
                if (r0 < rowEnd) {
                    __half2 v = __floats2half2_rn(siluf(p[0] + b0), siluf(p[1] + b1));
                    *(__half2*)(g_dhh + (size_t)r0 * DDIM + cc) = v;
                }
                if (r0 + 8 < rowEnd) {
                    __half2 v = __floats2half2_rn(siluf(p[2] + b0), siluf(p[3] + b1));
                    *(__half2*)(g_dhh + (size_t)(r0 + 8) * DDIM + cc) = v;
                }
            }
        }
    }
}

// ---------------- enc layer1 mma (gathered rows, BN=64) ----------------
__global__ void __launch_bounds__(256)
enc1_kernel(const float* __restrict__ enc_b1)
{
    int e = blockIdx.z;
    int segEnd = g_off[e + 1];
    int rowBase = g_off[e] + blockIdx.y * BM;
    if (rowBase >= segEnd) return;

    extern __shared__ char smem[];
    __shared__ int sidx[BM];
    uint32_t sb = smem_u32(smem);
    int tid = threadIdx.x, lane = tid & 31, wid = tid >> 5;
    int wm = (wid & 3) * 32, wn = (wid >> 2) * 32;

    for (int i = tid; i < BM; i += 256) {
        int p = rowBase + i; if (p > segEnd - 1) p = segEnd - 1;
        sidx[i] = g_idx[p];
    }
    __syncthreads();

    const __half* Bw = g_we1t + (size_t)e * ND * DDIM;

    float acc[2][4][4];
    #pragma unroll
    for (int i = 0; i < 2; i++)
        #pragma unroll
        for (int j = 0; j < 4; j++)
            #pragma unroll
            for (int q = 0; q < 4; q++) acc[i][j][q] = 0.f;

    const __half* gsrc[3];
    uint32_t sdst[3];
    #pragma unroll
    for (int p = 0; p < 3; p++) {
        int q = p * 256 + tid;
        if (q < 512) {
            int row = q >> 2, c = q & 3;
            sdst[p] = swz(row * 64 + c * 16);
            gsrc[p] = g_xh + (size_t)sidx[row] * DDIM + c * 8;
        } else {
            int i = q - 512;
            int row = i >> 2, c = i & 3;
            sdst[p] = E1_OFFB + swz(row * 64 + c * 16);
            gsrc[p] = Bw + (size_t)row * DDIM + c * 8;
        }
    }
    auto load_stage = [&](uint32_t stOff) {
        #pragma unroll
        for (int p = 0; p < 3; p++) {
            cpa16(sb + stOff + sdst[p], gsrc[p]);
            gsrc[p] += 32;
        }
        asm volatile("cp.async.commit_group;" ::: "memory");
    };

    load_stage(0);
    load_stage(E1_STAGE);

    int lr = lane & 15, lcb = (lane >> 4) << 4;
    uint32_t aAddr[2], bAddr[2];
    #pragma unroll
    for (int mt = 0; mt < 2; mt++) aAddr[mt] = ldm_addr(wm + mt * 16 + lr, lcb);
    #pragma unroll
    for (int bt = 0; bt < 2; bt++) bAddr[bt] = E1_OFFB + ldm_addr(wn + bt * 16 + lr, lcb);

    uint32_t stOff = 0, ldOff = 2 * E1_STAGE;
    for (int ck = 0; ck < 64; ck++) {
        if (ck < 63) asm volatile("cp.async.wait_group 1;" ::: "memory");
        else         asm volatile("cp.async.wait_group 0;" ::: "memory");
        __syncthreads();
        if (ck + 2 < 64) {
            load_stage(ldOff);
            ldOff += E1_STAGE; if (ldOff == 3 * E1_STAGE) ldOff = 0;
        }
        uint32_t st = sb + stOff;
        stOff += E1_STAGE; if (stOff == 3 * E1_STAGE) stOff = 0;

        #pragma unroll
        for (int ks = 0; ks < 2; ks++) {
            uint32_t kx = ks << 5;
            uint32_t ah[2][4], bh[2][4];
            #pragma unroll
            for (int mt = 0; mt < 2; mt++) ldm4(ah[mt], st + (aAddr[mt] ^ kx));
            #pragma unroll
            for (int bt = 0; bt < 2; bt++) ldm4(bh[bt], st + (bAddr[bt] ^ kx));
            #pragma unroll
            for (int mt = 0; mt < 2; mt++)
                #pragma unroll
                for (int nt = 0; nt < 4; nt++) {
                    int bt = nt >> 1, ss = nt & 1;
                    mma16816(acc[mt][nt], ah[mt], bh[bt][ss], bh[bt][ss + 2]);
                }
        }
    }

    #pragma unroll
    for (int nt = 0; nt < 4; nt++) {
        int lc = wn + nt * 8 + (lane & 3) * 2;
        float b0 = enc_b1[e * ND + lc], b1 = enc_b1[e * ND + lc + 1];
        #pragma unroll
        for (int mt = 0; mt < 2; mt++) {
            int r0 = rowBase + wm + mt * 16 + (lane >> 2);
            float* p = acc[mt][nt];
            if (r0 < segEnd) {
                __half2 v = __floats2half2_rn(siluf(p[0] + b0), siluf(p[1] + b1));
                *(__half2*)(g_h1 + (size_t)r0 * ND + lc) = v;
            }
            if (r0 + 8 < segEnd) {
                __half2 v = __floats2half2_rn(siluf(p[2] + b0), siluf(p[3] + b1));
                *(__half2*)(g_h1 + (size_t)(r0 + 8) * ND + lc) = v;
            }
        }
    }
}

// ---------------- enc layer2 + reparam ----------------
__global__ void __launch_bounds__(256)
enc2_kernel(const float* __restrict__ eps,
            const float* __restrict__ enc_w2, const float* __restrict__ enc_b2,
            float* __restrict__ out_noise, float* __restrict__ out_mean,
            float* __restrict__ out_lv)
{
    int e = blockIdx.z;
    int r0 = g_off[e] + blockIdx.x * 32;
    int rEnd = g_off[e + 1];
    if (r0 >= rEnd) return;
    int nt = rEnd - r0; if (nt > 32) nt = 32;

    __shared__ int   tids[32];
    __shared__ float Hs[32][65];
    __shared__ float Ps[32][129];

    int tid = threadIdx.x;
    if (tid < 32) tids[tid] = (tid < nt) ? g_idx[r0 + tid] : g_idx[r0];
    for (int q = tid; q < 32 * ND; q += 256) {
        int row = q >> 6, nd = q & 63;
        Hs[row][nd] = __half2float(g_h1[(size_t)(r0 + (row < nt ? row : 0)) * ND + nd]);
    }
    __syncthreads();

    int n2 = tid & 127;
    int g2 = tid >> 7;
    float acc2[16];
    #pragma unroll
    for (int j = 0; j < 16; j++) acc2[j] = 0.f;
    const float* w2 = enc_w2 + (size_t)e * ND * 2 * ND;
    #pragma unroll 4
    for (int k = 0; k < ND; k++) {
        float w = w2[k * 128 + n2];
        #pragma unroll
        for (int j = 0; j < 16; j++)
            acc2[j] += Hs[g2 * 16 + j][k] * w;
    }
    float b2v = enc_b2[e * 128 + n2];
    #pragma unroll
    for (int j = 0; j < 16; j++)
        Ps[g2 * 16 + j][n2] = acc2[j] + b2v;
    __syncthreads();

    for (int q = tid; q < nt * ND; q += 256) {
        int tok = q >> 6;
        int nd  = q & 63;
        float mean = Ps[tok][nd];
        float lv   = Ps[tok][nd + 64];
        int t = tids[tok];
        float ns = eps[(size_t)t * ND + nd] * expf(0.5f * lv) + mean;
        out_mean[(size_t)t * ND + nd]  = mean;
        out_lv[(size_t)t * ND + nd]    = lv;
        out_noise[(size_t)t * ND + nd] = ns;
        g_nh[(size_t)(r0 + tok) * ND + nd] = __float2half_rn(ns);
    }
}

// ---------------- heads ----------------
__global__ void __launch_bounds__(256)
heads_lite_kernel(const float* __restrict__ cls_b2, const float* __restrict__ var_b2)
{
    int t = blockIdx.x * 256 + threadIdx.x;
    if (t >= T_TOK) return;
    const float* hp = g_hpart + (size_t)t * 48;
    float a[3] = {cls_b2[0], cls_b2[1], cls_b2[2]};
    #pragma unroll
    for (int bx = 0; bx < 8; bx++) {
        a[0] += hp[bx * 3 + 0];
        a[1] += hp[bx * 3 + 1];
        a[2] += hp[bx * 3 + 2];
    }
    float av = var_b2[0];
    #pragma unroll
    for (int bx = 8; bx < 16; bx++) av += hp[bx * 3];

    int best = 0;
    if (a[1] > a[best]) best = 1;
    if (a[2] > a[best]) best = 2;
    float second = -1e30f;
    #pragma unroll
    for (int c = 0; c < 3; c++) if (c != best && a[c] > second) second = a[c];
    g_sel[t] = best;
    g_strength[t] = 1.f / (1.f + expf(-av));
    atomicAdd(&g_cnt[best], 1);
    if (a[best] - second < 3e-3f) {
        int p = atomicAdd(&g_fix_n, 1);
        if (p < FIXCAP) g_fix[p] = t;
    }
}

// ---------------- batched exact fp32 fixup (16 tokens/group) ----------------
__global__ void __launch_bounds__(256)
fixup_h_kernel(const float* __restrict__ x,
               const float* __restrict__ cls_w1, const float* __restrict__ cls_b1,
               const float* __restrict__ cls_w2)
{
    int nfix = g_fix_n; if (nfix > FIXCAP) nfix = FIXCAP;
    if (nfix == 0) return;
    int ngrp = (nfix + 15) >> 4;

    int col = blockIdx.y * 256 + threadIdx.x;
    float w20 = cls_w2[col * 3 + 0];
    float w21 = cls_w2[col * 3 + 1];
    float w22 = cls_w2[col * 3 + 2];
    float bc = cls_b1[col];

    __shared__ float xs[16][512];
    __shared__ int toks[16];
    __shared__ float red[8][16][3];
    int tid = threadIdx.x, lane = tid & 31, wd = tid >> 5;

    for (int g = blockIdx.x; g < ngrp; g += gridDim.x) {
        int base = g * 16;
        int cnt = nfix - base; if (cnt > 16) cnt = 16;
        __syncthreads();
        if (tid < 16) toks[tid] = g_fix[base + (tid < cnt ? tid : 0)];
        __syncthreads();

        float acc[16];
        #pragma unroll
        for (int t = 0; t < 16; t++) acc[t] = 0.f;

        for (int kc = 0; kc < 4; kc++) {
            #pragma unroll
            for (int p = 0; p < 8; p++) {
                int idx = p * 256 + tid;        // 2048 float4 slots
                int t16 = idx >> 7;
                int c4 = (idx & 127) << 2;
                float4 v = *(const float4*)(x + (size_t)toks[t16] * DDIM + kc * 512 + c4);
                *(float4*)&xs[t16][c4] = v;
            }
            __syncthreads();
            for (int k = 0; k < 512; k++) {
                float w = cls_w1[(size_t)(kc * 512 + k) * DHALF + col];
                #pragma unroll
                for (int t = 0; t < 16; t++) acc[t] += xs[t][k] * w;
            }
            __syncthreads();
        }

        #pragma unroll
        for (int t = 0; t < 16; t++) {
            float hv = siluf(acc[t] + bc);
            float p0 = hv * w20, p1 = hv * w21, p2 = hv * w22;
            #pragma unroll
            for (int o = 16; o; o >>= 1) {
                p0 += __shfl_down_sync(0xffffffffu, p0, o);
                p1 += __shfl_down_sync(0xffffffffu, p1, o);
                p2 += __shfl_down_sync(0xffffffffu, p2, o);
            }
            if (lane == 0) { red[wd][t][0] = p0; red[wd][t][1] = p1; red[wd][t][2] = p2; }
        }
        __syncthreads();
        if (tid < 48) {
            int t = tid / 3, j = tid % 3;
            if (t < cnt) {
                float s = 0.f;
                #pragma unroll
                for (int q = 0; q < 8; q++) s += red[q][t][j];
                g_fixlog[(size_t)(base + t) * 12 + blockIdx.y * 3 + j] = s;
            }
        }
    }
}

__global__ void fixup_sel_kernel(const float* __restrict__ cls_b2) {
    int i = blockIdx.x * 256 + threadIdx.x;
    int nfix = g_fix_n; if (nfix > FIXCAP) nfix = FIXCAP;
    if (i >= nfix) return;
    float a[3];
    #pragma unroll
    for (int j = 0; j < 3; j++) {
        float s = cls_b2[j];
        #pragma unroll
        for (int q = 0; q < 4; q++) s += g_fixlog[(size_t)i * 12 + q * 3 + j];
        a[j] = s;
    }
    int best = 0;
    if (a[1] > a[best]) best = 1;
    if (a[2] > a[best]) best = 2;
    int t = g_fix[i];
    int old = g_sel[t];
    if (old != best) {
        atomicSub(&g_cnt[old], 1);
        atomicAdd(&g_cnt[best], 1);
        g_sel[t] = best;
    }
}

// ---------------- LayerNorm + residual epilogue (fp16 g_do) ----------------
__global__ void __launch_bounds__(256)
ln_out_kernel(const float* __restrict__ x, const float* __restrict__ ln_g,
              const float* __restrict__ ln_b, float* __restrict__ out)
{
    int r = blockIdx.x;
    int e = (r >= g_off[1]) + (r >= g_off[2]);
    int t = g_idx[r];
    const __half* row = g_do + (size_t)r * DDIM;
    int tid = threadIdx.x;
    int c = tid << 2;

    uint2 u0 = *(const uint2*)(row + c);
    uint2 u1 = *(const uint2*)(row + 1024 + c);
    float2 f00 = __half22float2(*(__half2*)&u0.x);
    float2 f01 = __half22float2(*(__half2*)&u0.y);
    float2 f10 = __half22float2(*(__half2*)&u1.x);
    float2 f11 = __half22float2(*(__half2*)&u1.y);
    float4 v0 = make_float4(f00.x, f00.y, f01.x, f01.y);
    float4 v1 = make_float4(f10.x, f10.y, f11.x, f11.y);

    float s1 = v0.x + v0.y + v0.z + v0.w + v1.x + v1.y + v1.z + v1.w;
    float s2 = v0.x * v0.x + v0.y * v0.y + v0.z * v0.z + v0.w * v0.w
             + v1.x * v1.x + v1.y * v1.y + v1.z * v1.z + v1.w * v1.w;

    __shared__ float red[8][2];
    __shared__ float stats[2];
    int lane = tid & 31, w = tid >> 5;
    #pragma unroll
    for (int o = 16; o; o >>= 1) {
        s1 += __shfl_down_sync(0xffffffffu, s1, o);
        s2 += __shfl_down_sync(0xffffffffu, s2, o);
    }
    if (lane == 0) { red[w][0] = s1; red[w][1] = s2; }
    __syncthreads();
    if (tid == 0) {
        float a1 = 0.f, a2 = 0.f;
        for (int q = 0; q < 8; q++) { a1 += red[q][0]; a2 += red[q][1]; }
        float mu = a1 * (1.f / DDIM);
        float var = a2 * (1.f / DDIM) - mu * mu;
        if (var < 0.f) var = 0.f;
        stats[0] = mu;
        stats[1] = rsqrtf(var + LN_EPS);
    }
    __syncthreads();
    float mu = stats[0], rstd = stats[1];
    float s = g_strength[t];

    const float* xr = x + (size_t)t * DDIM;
    const float* gg = ln_g + (size_t)e * DDIM;
    const float* bb = ln_b + (size_t)e * DDIM;
    float* orow = out + (size_t)t * DDIM;

    float4 xv, gv, bv, ov;
    xv = *(const float4*)(xr + c); gv = *(const float4*)(gg + c); bv = *(const float4*)(bb + c);
    ov.x = xv.x + s * ((v0.x - mu) * rstd * gv.x + bv.x);
    ov.y = xv.y + s * ((v0.y - mu) * rstd * gv.y + bv.y);
    ov.z = xv.z + s * ((v0.z - mu) * rstd * gv.z + bv.z);
    ov.w = xv.w + s * ((v0.w - mu) * rstd * gv.w + bv.w);
    *(float4*)(orow + c) = ov;
    xv = *(const float4*)(xr + 1024 + c); gv = *(const float4*)(gg + 1024 + c); bv = *(const float4*)(bb + 1024 + c);
    ov.x = xv.x + s * ((v1.x - mu) * rstd * gv.x + bv.x);
    ov.y = xv.y + s * ((v1.y - mu) * rstd * gv.y + bv.y);
    ov.z = xv.z + s * ((v1.z - mu) * rstd * gv.z + bv.z);
    ov.w = xv.w + s * ((v1.w - mu) * rstd * gv.w + bv.w);
    *(float4*)(orow + 1024 + c) = ov;
}

// ---------------- launch ----------------
extern "C" void kernel_launch(void* const* d_in, const int* in_sizes, int n_in,
                              void* d_out, int out_size)
{
    const float* x       = (const float*)d_in[0];
    const float* eps     = (const float*)d_in[1];
    const float* cls_w1  = (const float*)d_in[2];
    const float* cls_b1  = (const float*)d_in[3];
    const float* cls_w2  = (const float*)d_in[4];
    const float* cls_b2  = (const float*)d_in[5];
    const float* var_w1  = (const float*)d_in[6];
    const float* var_b1  = (const float*)d_in[7];
    const float* var_w2  = (const float*)d_in[8];
    const float* var_b2  = (const float*)d_in[9];
    const float* enc_w1  = (const float*)d_in[10];
    const float* enc_b1  = (const float*)d_in[11];
    const float* enc_w2  = (const float*)d_in[12];
    const float* enc_b2  = (const float*)d_in[13];
    const float* dec_w1  = (const float*)d_in[14];
    const float* dec_b1  = (const float*)d_in[15];
    const float* dec_w2  = (const float*)d_in[16];
    const float* dec_b2  = (const float*)d_in[17];
    const float* ln_g    = (const float*)d_in[18];
    const float* ln_b    = (const float*)d_in[19];

    float* out       = (float*)d_out;
    float* out_noise = out + (size_t)T_TOK * DDIM;
    float* out_mean  = out_noise + (size_t)T_TOK * ND;
    float* out_lv    = out_mean + (size_t)T_TOK * ND;

    cudaFuncSetAttribute(mma_gemm_kernel<0>, cudaFuncAttributeMaxDynamicSharedMemorySize, GEMM_SMEM);
    cudaFuncSetAttribute(mma_gemm_kernel<1>, cudaFuncAttributeMaxDynamicSharedMemorySize, GEMM_SMEM);
    cudaFuncSetAttribute(mma_gemm_kernel<2>, cudaFuncAttributeMaxDynamicSharedMemorySize, GEMM_SMEM);
    cudaFuncSetAttribute(enc1_kernel, cudaFuncAttributeMaxDynamicSharedMemorySize, E1_SMEM);

    split_x_kernel<<<((size_t)T_TOK * DDIM) / 2048, 256>>>(x);        // + init
    conv_w1t_kernel<<<dim3(64, 64), 256>>>(cls_w1, var_w1, cls_b1, var_b1);  // + bias fuse

    // stage 1
    mma_gemm_kernel<0><<<dim3(DDIM / BN, T_TOK / BM, 1), 256, GEMM_SMEM>>>(dec_b2, dec_b1, cls_w2, var_w2);

    conv_w2t_kernel<<<dim3(64, 64, NE), 256>>>(dec_w2);
    conv_we1t_kernel<<<dim3(2, 64, NE), 256>>>(enc_w1);
    conv_wd1t_kernel<<<dim3(64, 2, NE), 256>>>(dec_w1);

    heads_lite_kernel<<<T_TOK / 256, 256>>>(cls_b2, var_b2);
    fixup_h_kernel<<<dim3(32, 4), 256>>>(x, cls_w1, cls_b1, cls_w2);
    fixup_sel_kernel<<<FIXCAP / 256, 256>>>(cls_b2);
    scatter_kernel<<<T_TOK / 256, 256>>>();                           // + scan

    enc1_kernel<<<dim3(1, T_TOK / BM, NE), 256, E1_SMEM>>>(enc_b1);
    enc2_kernel<<<dim3(512, 1, NE), 256>>>(eps, enc_w2, enc_b2, out_noise, out_mean, out_lv);

    mma_gemm_kernel<2><<<dim3(DDIM / BN, T_TOK / BM, NE), 256, GEMM_SMEM>>>(dec_b2, dec_b1, cls_w2, var_w2);
    mma_gemm_kernel<1><<<dim3(DDIM / BN, T_TOK / BM, NE), 256, GEMM_SMEM>>>(dec_b2, dec_b1, cls_w2, var_w2);

    ln_out_kernel<<<T_TOK, 256>>>(x, ln_g, ln_b, out);
}

// round 17
// speedup vs baseline: 1.2133x; 1.2133x over previous
#include <cuda_runtime.h>
#include <cuda_fp16.h>
#include <math.h>
#include <stdint.h>

#define T_TOK 16384
#define DDIM  2048
#define DHALF 1024
#define ND    64
#define NE    3
#define LN_EPS 1e-5f
#define FIXCAP 4096

// mma.sync GEMM tiling — BM=128, BN=128, BK=64 (best measured config)
#define BM 128
#define BN 128
#define BKC 64
#define STAGE_B 32768
#define OFF_B 16384
#define GEMM_SMEM (3 * STAGE_B)  // 98304

// enc1 tiling (BN=64, BK=32)
#define E1_STAGE 12288
#define E1_OFFB 8192
#define E1_SMEM (3 * E1_STAGE)

// -------- device scratch --------
__device__ __half g_do[(size_t)T_TOK * DDIM];
__device__ float g_strength[T_TOK];
__device__ float g_hpart[(size_t)T_TOK * 48];
__device__ int   g_sel[T_TOK];
__device__ int   g_idx[T_TOK];
__device__ int   g_cnt[NE];
__device__ int   g_cur[NE];
__device__ int   g_off[NE + 1];
__device__ int   g_fix_n;
__device__ int   g_fix[FIXCAP];
__device__ float g_fixlog[FIXCAP * 12];

__device__ __half g_xh[(size_t)T_TOK * DDIM];
__device__ __half g_dhh[(size_t)(T_TOK + 256) * DDIM];
__device__ __half g_h1[(size_t)(T_TOK + 256) * ND];
__device__ __half g_nh[(size_t)(T_TOK + 256) * ND];
__device__ __half g_w1h[(size_t)DDIM * DDIM];
__device__ __half g_w2h[(size_t)NE * DDIM * DDIM];
__device__ __half g_we1t[(size_t)NE * ND * DDIM];
__device__ __half g_wd1t[(size_t)NE * DDIM * ND];
__device__ float g_b1f[DDIM];

__device__ __forceinline__ float siluf(float v) { return v / (1.f + expf(-v)); }

__device__ __forceinline__ uint32_t smem_u32(const void* p) {
    uint32_t a;
    asm("{ .reg .u64 t; cvta.to.shared.u64 t, %1; cvt.u32.u64 %0, t; }" : "=r"(a) : "l"(p));
    return a;
}
__device__ __forceinline__ void cpa16(uint32_t dst, const void* src) {
    asm volatile("cp.async.cg.shared.global [%0], [%1], 16;" :: "r"(dst), "l"(src) : "memory");
}
__device__ __forceinline__ void ldm4(uint32_t* r, uint32_t addr) {
    asm volatile("ldmatrix.sync.aligned.m8n8.x4.shared.b16 {%0,%1,%2,%3}, [%4];"
        : "=r"(r[0]), "=r"(r[1]), "=r"(r[2]), "=r"(r[3]) : "r"(addr));
}
__device__ __forceinline__ void mma16816(float* c, const uint32_t* a, uint32_t b0, uint32_t b1) {
    asm volatile("mma.sync.aligned.m16n8k16.row.col.f32.f16.f16.f32 "
        "{%0,%1,%2,%3}, {%4,%5,%6,%7}, {%8,%9}, {%0,%1,%2,%3};"
        : "+f"(c[0]), "+f"(c[1]), "+f"(c[2]), "+f"(c[3])
        : "r"(a[0]), "r"(a[1]), "r"(a[2]), "r"(a[3]), "r"(b0), "r"(b1));
}
__device__ __forceinline__ uint32_t swz(uint32_t off) { return off ^ ((off >> 3) & 0x30); }
__device__ __forceinline__ uint32_t ldm_addr(int row, int lcb) {
    return (uint32_t)(row * 64 + (lcb ^ ((row & 6) << 3)));
}

// ---------------- small kernels ----------------
__global__ void init_kernel() {
    int i = threadIdx.x;
    if (i < NE) { g_cnt[i] = 0; g_cur[i] = 0; }
    if (i == 0) g_fix_n = 0;
}
__global__ void scan_kernel() {
    g_off[0] = 0;
    g_off[1] = g_cnt[0];
    g_off[2] = g_cnt[0] + g_cnt[1];
    g_off[3] = g_cnt[0] + g_cnt[1] + g_cnt[2];
}
__global__ void scatter_kernel() {
    int t = blockIdx.x * 256 + threadIdx.x;
    if (t >= T_TOK) return;
    int e = g_sel[t];
    int p = atomicAdd(&g_cur[e], 1);
    g_idx[g_off[e] + p] = t;
}

__global__ void __launch_bounds__(256) split_x_kernel(const float* __restrict__ x) {
    size_t i = ((size_t)blockIdx.x * 256 + threadIdx.x) * 8;
    float4 a = *(const float4*)(x + i);
    float4 b = *(const float4*)(x + i + 4);
    __half2 h0 = __floats2half2_rn(a.x, a.y);
    __half2 h1 = __floats2half2_rn(a.z, a.w);
    __half2 h2 = __floats2half2_rn(b.x, b.y);
    __half2 h3 = __floats2half2_rn(b.z, b.w);
    uint4 o;
    o.x = *(uint32_t*)&h0; o.y = *(uint32_t*)&h1;
    o.z = *(uint32_t*)&h2; o.w = *(uint32_t*)&h3;
    *(uint4*)(g_xh + i) = o;
}

__global__ void __launch_bounds__(256)
conv_w1t_kernel(const float* __restrict__ cls_w1, const float* __restrict__ var_w1) {
    __shared__ float tile[32][33];
    int n0 = blockIdx.x * 32, k0 = blockIdx.y * 32;
    int tx = threadIdx.x & 31, ty = threadIdx.x >> 5;
    for (int r = ty; r < 32; r += 8) {
        int k = k0 + r, n = n0 + tx;
        tile[r][tx] = (n < DHALF) ? cls_w1[(size_t)k * DHALF + n]
                                  : var_w1[(size_t)k * DHALF + n - DHALF];
    }
    __syncthreads();
    for (int r = ty; r < 32; r += 8)
        g_w1h[(size_t)(n0 + r) * DDIM + k0 + tx] = __float2half_rn(tile[tx][r]);
}

__global__ void __launch_bounds__(256)
conv_w2t_kernel(const float* __restrict__ w2) {
    __shared__ float tile[32][33];
    int e = blockIdx.z;
    int n0 = blockIdx.x * 32, k0 = blockIdx.y * 32;
    int tx = threadIdx.x & 31, ty = threadIdx.x >> 5;
    const float* src = w2 + (size_t)e * DDIM * DDIM;
    for (int r = ty; r < 32; r += 8)
        tile[r][tx] = src[(size_t)(k0 + r) * DDIM + n0 + tx];
    __syncthreads();
    __half* dh = g_w2h + (size_t)e * DDIM * DDIM;
    for (int r = ty; r < 32; r += 8)
        dh[(size_t)(n0 + r) * DDIM + k0 + tx] = __float2half_rn(tile[tx][r]);
}

__global__ void __launch_bounds__(256)
conv_we1t_kernel(const float* __restrict__ w) {
    __shared__ float tile[32][33];
    int e = blockIdx.z;
    int n0 = blockIdx.x * 32, k0 = blockIdx.y * 32;
    int tx = threadIdx.x & 31, ty = threadIdx.x >> 5;
    const float* src = w + (size_t)e * DDIM * ND;
    for (int r = ty; r < 32; r += 8)
        tile[r][tx] = src[(size_t)(k0 + r) * ND + n0 + tx];
    __syncthreads();
    __half* dst = g_we1t + (size_t)e * ND * DDIM;
    for (int r = ty; r < 32; r += 8)
        dst[(size_t)(n0 + r) * DDIM + k0 + tx] = __float2half_rn(tile[tx][r]);
}

__global__ void __launch_bounds__(256)
conv_wd1t_kernel(const float* __restrict__ w) {
    __shared__ float tile[32][33];
    int e = blockIdx.z;
    int n0 = blockIdx.x * 32, k0 = blockIdx.y * 32;
    int tx = threadIdx.x & 31, ty = threadIdx.x >> 5;
    const float* src = w + (size_t)e * ND * DDIM;
    for (int r = ty; r < 32; r += 8)
        tile[r][tx] = src[(size_t)(k0 + r) * DDIM + n0 + tx];
    __syncthreads();
    __half* dst = g_wd1t + (size_t)e * DDIM * ND;
    for (int r = ty; r < 32; r += 8)
        dst[(size_t)(n0 + r) * ND + k0 + tx] = __float2half_rn(tile[tx][r]);
}

__global__ void bias_fuse_kernel(const float* __restrict__ cls_b1, const float* __restrict__ var_b1) {
    int j = blockIdx.x * 256 + threadIdx.x;
    if (j < DDIM) g_b1f[j] = (j < DHALF) ? cls_b1[j] : var_b1[j - DHALF];
}

// ---------------- mma.sync fp16 GEMM (BK=64, hoisted addressing) ----------------
template <int MODE>
__global__ void __launch_bounds__(256)
mma_gemm_kernel(const float* __restrict__ dec_b2, const float* __restrict__ dec_b1,
                const float* __restrict__ cls_w2p, const float* __restrict__ var_w2p)
{
    constexpr int KD  = (MODE == 2) ? 64 : 2048;
    constexpr int LDA = (MODE == 2) ? 64 : 2048;
    constexpr int LDB = (MODE == 2) ? 64 : 2048;
    constexpr int NCHm = KD / BKC;

    int colBase = blockIdx.x * BN;
    int rowBase, rowEnd;
    const __half *Ah, *Bh;
    const float* bp;
    if (MODE == 0) {
        rowBase = blockIdx.y * BM; rowEnd = T_TOK;
        Ah = g_xh; Bh = g_w1h; bp = g_b1f;
    } else {
        int e = blockIdx.z;
        rowEnd = g_off[e + 1];
        rowBase = g_off[e] + blockIdx.y * BM;
        if (rowBase >= rowEnd) return;
        if (MODE == 1) {
            Ah = g_dhh; Bh = g_w2h + (size_t)e * DDIM * DDIM; bp = dec_b2 + e * DDIM;
        } else {
            Ah = g_nh; Bh = g_wd1t + (size_t)e * DDIM * ND; bp = dec_b1 + e * DDIM;
        }
    }

    extern __shared__ char smem[];
    uint32_t sb = smem_u32(smem);
    int tid = threadIdx.x, lane = tid & 31, wid = tid >> 5;
    int wm = (wid & 1) * 64, wn = (wid >> 1) * 32;

    float acc[4][4][4];
    #pragma unroll
    for (int i = 0; i < 4; i++)
        #pragma unroll
        for (int j = 0; j < 4; j++)
            #pragma unroll
            for (int q = 0; q < 4; q++) acc[i][j][q] = 0.f;

    const __half* gsrc[4];
    uint32_t sdst[4];
    {
        int row0 = tid >> 2, c = tid & 3;
        int row1 = row0 + 64;
        uint32_t d0 = swz(row0 * 64 + c * 16);
        uint32_t d1 = swz(row1 * 64 + c * 16);
        sdst[0] = d0;            gsrc[0] = Ah + (size_t)(rowBase + row0) * LDA + c * 8;
        sdst[1] = d1;            gsrc[1] = Ah + (size_t)(rowBase + row1) * LDA + c * 8;
        sdst[2] = OFF_B + d0;    gsrc[2] = Bh + (size_t)(colBase + row0) * LDB + c * 8;
        sdst[3] = OFF_B + d1;    gsrc[3] = Bh + (size_t)(colBase + row1) * LDB + c * 8;
    }
    auto load_stage = [&](uint32_t stOff) {
        #pragma unroll
        for (int p = 0; p < 4; p++) {
            cpa16(sb + stOff + sdst[p], gsrc[p]);
            cpa16(sb + stOff + sdst[p] + 8192, gsrc[p] + 32);
            gsrc[p] += BKC;
        }
        asm volatile("cp.async.commit_group;" ::: "memory");
    };

    load_stage(0);
    if (NCHm > 1) load_stage(STAGE_B);

    int lr = lane & 15, lcb = (lane >> 4) << 4;
    uint32_t aAddr[4], bAddr[2];
    #pragma unroll
    for (int mt = 0; mt < 4; mt++) aAddr[mt] = ldm_addr(wm + mt * 16 + lr, lcb);
    #pragma unroll
    for (int bt = 0; bt < 2; bt++) bAddr[bt] = OFF_B + ldm_addr(wn + bt * 16 + lr, lcb);

    uint32_t stOff = 0, ldOff = 2 * STAGE_B;
    for (int ck = 0; ck < NCHm; ck++) {
        if (NCHm > 1 && ck < NCHm - 1) asm volatile("cp.async.wait_group 1;" ::: "memory");
        else                           asm volatile("cp.async.wait_group 0;" ::: "memory");
        __syncthreads();
        if (ck + 2 < NCHm) {
            load_stage(ldOff);
            ldOff += STAGE_B; if (ldOff == 3 * STAGE_B) ldOff = 0;
        }
        uint32_t st = sb + stOff;
        stOff += STAGE_B; if (stOff == 3 * STAGE_B) stOff = 0;

        #pragma unroll
        for (int ks = 0; ks < 4; ks++) {
            uint32_t base = st + ((ks >> 1) << 13);
            uint32_t kx = (ks & 1) << 5;
            uint32_t ah[4][4], bh[2][4];
            #pragma unroll
            for (int mt = 0; mt < 4; mt++) ldm4(ah[mt], base + (aAddr[mt] ^ kx));
            #pragma unroll
            for (int bt = 0; bt < 2; bt++) ldm4(bh[bt], base + (bAddr[bt] ^ kx));
            #pragma unroll
            for (int mt = 0; mt < 4; mt++)
                #pragma unroll
                for (int nt = 0; nt < 4; nt++) {
                    int bt = nt >> 1, ss = nt & 1;
                    mma16816(acc[mt][nt], ah[mt], bh[bt][ss], bh[bt][ss + 2]);
                }
        }
    }

    if (MODE == 0) {
        __syncthreads();
        float* sred = (float*)smem;
        float* w2s  = (float*)(smem + 8192);
        float* bs   = (float*)(smem + 8192 + 2048);
        bool isCls = (colBase < DHALF);
        if (isCls) {
            for (int j = tid; j < 384; j += 256) w2s[j] = cls_w2p[colBase * 3 + j];
        } else {
            for (int j = tid; j < 128; j += 256) w2s[j] = var_w2p[colBase - DHALF + j];
        }
        for (int j = tid; j < 128; j += 256) bs[j] = bp[colBase + j];
        __syncthreads();

        float ps[4][2][3];
        #pragma unroll
        for (int mt = 0; mt < 4; mt++)
            #pragma unroll
            for (int hh = 0; hh < 2; hh++)
                #pragma unroll
                for (int j = 0; j < 3; j++) ps[mt][hh][j] = 0.f;

        #pragma unroll
        for (int mt = 0; mt < 4; mt++)
            #pragma unroll
            for (int nt = 0; nt < 4; nt++) {
                int lc = wn + nt * 8 + (lane & 3) * 2;
                float b0 = bs[lc], b1 = bs[lc + 1];
                float h00 = siluf(acc[mt][nt][0] + b0);
                float h01 = siluf(acc[mt][nt][1] + b1);
                float h10 = siluf(acc[mt][nt][2] + b0);
                float h11 = siluf(acc[mt][nt][3] + b1);
                if (isCls) {
                    #pragma unroll
                    for (int j = 0; j < 3; j++) {
                        ps[mt][0][j] += h00 * w2s[lc * 3 + j] + h01 * w2s[(lc + 1) * 3 + j];
                        ps[mt][1][j] += h10 * w2s[lc * 3 + j] + h11 * w2s[(lc + 1) * 3 + j];
                    }
                } else {
                    ps[mt][0][0] += h00 * w2s[lc] + h01 * w2s[lc + 1];
                    ps[mt][1][0] += h10 * w2s[lc] + h11 * w2s[lc + 1];
                }
            }

        #pragma unroll
        for (int mt = 0; mt < 4; mt++)
            #pragma unroll
            for (int hh = 0; hh < 2; hh++)
                #pragma unroll
                for (int j = 0; j < 3; j++) {
                    float v = ps[mt][hh][j];
                    v += __shfl_xor_sync(0xffffffffu, v, 1);
                    v += __shfl_xor_sync(0xffffffffu, v, 2);
                    if ((lane & 3) == 0) {
                        int rloc = wm + mt * 16 + (lane >> 2) + hh * 8;
                        sred[((wid >> 1) * 128 + rloc) * 3 + j] = v;
                    }
                }
        __syncthreads();
        for (int idx = tid; idx < 384; idx += 256) {
            int row = idx / 3, j = idx % 3;
            float s = sred[row * 3 + j] + sred[384 + row * 3 + j]
                    + sred[768 + row * 3 + j] + sred[1152 + row * 3 + j];
            g_hpart[(size_t)(rowBase + row) * 48 + blockIdx.x * 3 + j] = s;
        }
        return;
    }

    #pragma unroll
    for (int nt = 0; nt < 4; nt++) {
        int cc = colBase + wn + nt * 8 + (lane & 3) * 2;
        float b0 = bp[cc], b1 = bp[cc + 1];
        #pragma unroll
        for (int mt = 0; mt < 4; mt++) {
            int r0 = rowBase + wm + mt * 16 + (lane >> 2);
            float* p = acc[mt][nt];
            if (MODE == 1) {
                if (r0 < rowEnd) {
                    __half2 v = __floats2half2_rn(p[0] + b0, p[1] + b1);
                    *(__half2*)(g_do + (size_t)r0 * DDIM + cc) = v;
                }
                if (r0 + 8 < rowEnd) {
                    __half2 v = __floats2half2_rn(p[2] + b0, p[3] + b1);
                    *(__half2*)(g_do + (size_t)(r0 + 8) * DDIM + cc) = v;
                }
            } else {
                if (r0 < rowEnd) {
                    __half2 v = __floats2half2_rn(siluf(p[0] + b0), siluf(p[1] + b1));
                    *(__half2*)(g_dhh + (size_t)r0 * DDIM + cc) = v;
                }
                if (r0 + 8 < rowEnd) {
                    __half2 v = __floats2half2_rn(siluf(p[2] + b0), siluf(p[3] + b1));
                    *(__half2*)(g_dhh + (size_t)(r0 + 8) * DDIM + cc) = v;
                }
            }
        }
    }
}

// ---------------- enc layer1 mma (gathered rows, BN=64) ----------------
__global__ void __launch_bounds__(256)
enc1_kernel(const float* __restrict__ enc_b1)
{
    int e = blockIdx.z;
    int segEnd = g_off[e + 1];
    int rowBase = g_off[e] + blockIdx.y * BM;
    if (rowBase >= segEnd) return;

    extern __shared__ char smem[];
    __shared__ int sidx[BM];
    uint32_t sb = smem_u32(smem);
    int tid = threadIdx.x, lane = tid & 31, wid = tid >> 5;
    int wm = (wid & 3) * 32, wn = (wid >> 2) * 32;

    for (int i = tid; i < BM; i += 256) {
        int p = rowBase + i; if (p > segEnd - 1) p = segEnd - 1;
        sidx[i] = g_idx[p];
    }
    __syncthreads();

    const __half* Bw = g_we1t + (size_t)e * ND * DDIM;

    float acc[2][4][4];
    #pragma unroll
    for (int i = 0; i < 2; i++)
        #pragma unroll
        for (int j = 0; j < 4; j++)
            #pragma unroll
            for (int q = 0; q < 4; q++) acc[i][j][q] = 0.f;

    const __half* gsrc[3];
    uint32_t sdst[3];
    #pragma unroll
    for (int p = 0; p < 3; p++) {
        int q = p * 256 + tid;
        if (q < 512) {
            int row = q >> 2, c = q & 3;
            sdst[p] = swz(row * 64 + c * 16);
            gsrc[p] = g_xh + (size_t)sidx[row] * DDIM + c * 8;
        } else {
            int i = q - 512;
            int row = i >> 2, c = i & 3;
            sdst[p] = E1_OFFB + swz(row * 64 + c * 16);
            gsrc[p] = Bw + (size_t)row * DDIM + c * 8;
        }
    }
    auto load_stage = [&](uint32_t stOff) {
        #pragma unroll
        for (int p = 0; p < 3; p++) {
            cpa16(sb + stOff + sdst[p], gsrc[p]);
            gsrc[p] += 32;
        }
        asm volatile("cp.async.commit_group;" ::: "memory");
    };

    load_stage(0);
    load_stage(E1_STAGE);

    int lr = lane & 15, lcb = (lane >> 4) << 4;
    uint32_t aAddr[2], bAddr[2];
    #pragma unroll
    for (int mt = 0; mt < 2; mt++) aAddr[mt] = ldm_addr(wm + mt * 16 + lr, lcb);
    #pragma unroll
    for (int bt = 0; bt < 2; bt++) bAddr[bt] = E1_OFFB + ldm_addr(wn + bt * 16 + lr, lcb);

    uint32_t stOff = 0, ldOff = 2 * E1_STAGE;
    for (int ck = 0; ck < 64; ck++) {
        if (ck < 63) asm volatile("cp.async.wait_group 1;" ::: "memory");
        else         asm volatile("cp.async.wait_group 0;" ::: "memory");
        __syncthreads();
        if (ck + 2 < 64) {
            load_stage(ldOff);
            ldOff += E1_STAGE; if (ldOff == 3 * E1_STAGE) ldOff = 0;
        }
        uint32_t st = sb + stOff;
        stOff += E1_STAGE; if (stOff == 3 * E1_STAGE) stOff = 0;

        #pragma unroll
        for (int ks = 0; ks < 2; ks++) {
            uint32_t kx = ks << 5;
            uint32_t ah[2][4], bh[2][4];
            #pragma unroll
            for (int mt = 0; mt < 2; mt++) ldm4(ah[mt], st + (aAddr[mt] ^ kx));
            #pragma unroll
            for (int bt = 0; bt < 2; bt++) ldm4(bh[bt], st + (bAddr[bt] ^ kx));
            #pragma unroll
            for (int mt = 0; mt < 2; mt++)
                #pragma unroll
                for (int nt = 0; nt < 4; nt++) {
                    int bt = nt >> 1, ss = nt & 1;
                    mma16816(acc[mt][nt], ah[mt], bh[bt][ss], bh[bt][ss + 2]);
                }
        }
    }

    #pragma unroll
    for (int nt = 0; nt < 4; nt++) {
        int lc = wn + nt * 8 + (lane & 3) * 2;
        float b0 = enc_b1[e * ND + lc], b1 = enc_b1[e * ND + lc + 1];
        #pragma unroll
        for (int mt = 0; mt < 2; mt++) {
            int r0 = rowBase + wm + mt * 16 + (lane >> 2);
            float* p = acc[mt][nt];
            if (r0 < segEnd) {
                __half2 v = __floats2half2_rn(siluf(p[0] + b0), siluf(p[1] + b1));
                *(__half2*)(g_h1 + (size_t)r0 * ND + lc) = v;
            }
            if (r0 + 8 < segEnd) {
                __half2 v = __floats2half2_rn(siluf(p[2] + b0), siluf(p[3] + b1));
                *(__half2*)(g_h1 + (size_t)(r0 + 8) * ND + lc) = v;
            }
        }
    }
}

// ---------------- enc layer2 + reparam ----------------
__global__ void __launch_bounds__(256)
enc2_kernel(const float* __restrict__ eps,
            const float* __restrict__ enc_w2, const float* __restrict__ enc_b2,
            float* __restrict__ out_noise, float* __restrict__ out_mean,
            float* __restrict__ out_lv)
{
    int e = blockIdx.z;
    int r0 = g_off[e] + blockIdx.x * 32;
    int rEnd = g_off[e + 1];
    if (r0 >= rEnd) return;
    int nt = rEnd - r0; if (nt > 32) nt = 32;

    __shared__ int   tids[32];
    __shared__ float Hs[32][65];
    __shared__ float Ps[32][129];

    int tid = threadIdx.x;
    if (tid < 32) tids[tid] = (tid < nt) ? g_idx[r0 + tid] : g_idx[r0];
    for (int q = tid; q < 32 * ND; q += 256) {
        int row = q >> 6, nd = q & 63;
        Hs[row][nd] = __half2float(g_h1[(size_t)(r0 + (row < nt ? row : 0)) * ND + nd]);
    }
    __syncthreads();

    int n2 = tid & 127;
    int g2 = tid >> 7;
    float acc2[16];
    #pragma unroll
    for (int j = 0; j < 16; j++) acc2[j] = 0.f;
    const float* w2 = enc_w2 + (size_t)e * ND * 2 * ND;
    #pragma unroll 4
    for (int k = 0; k < ND; k++) {
        float w = w2[k * 128 + n2];
        #pragma unroll
        for (int j = 0; j < 16; j++)
            acc2[j] += Hs[g2 * 16 + j][k] * w;
    }
    float b2v = enc_b2[e * 128 + n2];
    #pragma unroll
    for (int j = 0; j < 16; j++)
        Ps[g2 * 16 + j][n2] = acc2[j] + b2v;
    __syncthreads();

    for (int q = tid; q < nt * ND; q += 256) {
        int tok = q >> 6;
        int nd  = q & 63;
        float mean = Ps[tok][nd];
        float lv   = Ps[tok][nd + 64];
        int t = tids[tok];
        float ns = eps[(size_t)t * ND + nd] * expf(0.5f * lv) + mean;
        out_mean[(size_t)t * ND + nd]  = mean;
        out_lv[(size_t)t * ND + nd]    = lv;
        out_noise[(size_t)t * ND + nd] = ns;
        g_nh[(size_t)(r0 + tok) * ND + nd] = __float2half_rn(ns);
    }
}

// ---------------- heads ----------------
__global__ void __launch_bounds__(256)
heads_lite_kernel(const float* __restrict__ cls_b2, const float* __restrict__ var_b2)
{
    int t = blockIdx.x * 256 + threadIdx.x;
    if (t >= T_TOK) return;
    const float* hp = g_hpart + (size_t)t * 48;
    float a[3] = {cls_b2[0], cls_b2[1], cls_b2[2]};
    #pragma unroll
    for (int bx = 0; bx < 8; bx++) {
        a[0] += hp[bx * 3 + 0];
        a[1] += hp[bx * 3 + 1];
        a[2] += hp[bx * 3 + 2];
    }
    float av = var_b2[0];
    #pragma unroll
    for (int bx = 8; bx < 16; bx++) av += hp[bx * 3];

    int best = 0;
    if (a[1] > a[best]) best = 1;
    if (a[2] > a[best]) best = 2;
    float second = -1e30f;
    #pragma unroll
    for (int c = 0; c < 3; c++) if (c != best && a[c] > second) second = a[c];
    g_sel[t] = best;
    g_strength[t] = 1.f / (1.f + expf(-av));
    atomicAdd(&g_cnt[best], 1);
    if (a[best] - second < 2e-3f) {
        int p = atomicAdd(&g_fix_n, 1);
        if (p < FIXCAP) g_fix[p] = t;
    }
}

// ---------------- batched exact fp32 fixup (8 tokens/group) ----------------
__global__ void __launch_bounds__(256)
fixup_h_kernel(const float* __restrict__ x,
               const float* __restrict__ cls_w1, const float* __restrict__ cls_b1,
               const float* __restrict__ cls_w2)
{
    int nfix = g_fix_n; if (nfix > FIXCAP) nfix = FIXCAP;
    if (nfix == 0) return;
    int ngrp = (nfix + 7) >> 3;

    int col = blockIdx.y * 256 + threadIdx.x;
    float w20 = cls_w2[col * 3 + 0];
    float w21 = cls_w2[col * 3 + 1];
    float w22 = cls_w2[col * 3 + 2];
    float bc = cls_b1[col];

    __shared__ float xs[8][512];
    __shared__ int toks[8];
    __shared__ float red[8][8][3];
    int tid = threadIdx.x, lane = tid & 31, wd = tid >> 5;

    for (int g = blockIdx.x; g < ngrp; g += gridDim.x) {
        int base = g * 8;
        int cnt = nfix - base; if (cnt > 8) cnt = 8;
        __syncthreads();
        if (tid < 8) toks[tid] = g_fix[base + (tid < cnt ? tid : 0)];
        __syncthreads();

        float acc[8];
        #pragma unroll
        for (int t = 0; t < 8; t++) acc[t] = 0.f;

        for (int kc = 0; kc < 4; kc++) {
            #pragma unroll
            for (int p = 0; p < 4; p++) {
                int idx = p * 256 + tid;
                int t8 = idx >> 7;
                int c4 = (idx & 127) << 2;
                float4 v = *(const float4*)(x + (size_t)toks[t8] * DDIM + kc * 512 + c4);
                *(float4*)&xs[t8][c4] = v;
            }
            __syncthreads();
            for (int k = 0; k < 512; k++) {
                float w = cls_w1[(size_t)(kc * 512 + k) * DHALF + col];
                #pragma unroll
                for (int t = 0; t < 8; t++) acc[t] += xs[t][k] * w;
            }
            __syncthreads();
        }

        #pragma unroll
        for (int t = 0; t < 8; t++) {
            float hv = siluf(acc[t] + bc);
            float p0 = hv * w20, p1 = hv * w21, p2 = hv * w22;
            #pragma unroll
            for (int o = 16; o; o >>= 1) {
                p0 += __shfl_down_sync(0xffffffffu, p0, o);
                p1 += __shfl_down_sync(0xffffffffu, p1, o);
                p2 += __shfl_down_sync(0xffffffffu, p2, o);
            }
            if (lane == 0) { red[wd][t][0] = p0; red[wd][t][1] = p1; red[wd][t][2] = p2; }
        }
        __syncthreads();
        if (tid < 24) {
            int t = tid / 3, j = tid % 3;
            if (t < cnt) {
                float s = 0.f;
                #pragma unroll
                for (int q = 0; q < 8; q++) s += red[q][t][j];
                g_fixlog[(size_t)(base + t) * 12 + blockIdx.y * 3 + j] = s;
            }
        }
    }
}

__global__ void fixup_sel_kernel(const float* __restrict__ cls_b2) {
    int i = blockIdx.x * 256 + threadIdx.x;
    int nfix = g_fix_n; if (nfix > FIXCAP) nfix = FIXCAP;
    if (i >= nfix) return;
    float a[3];
    #pragma unroll
    for (int j = 0; j < 3; j++) {
        float s = cls_b2[j];
        #pragma unroll
        for (int q = 0; q < 4; q++) s += g_fixlog[(size_t)i * 12 + q * 3 + j];
        a[j] = s;
    }
    int best = 0;
    if (a[1] > a[best]) best = 1;
    if (a[2] > a[best]) best = 2;
    int t = g_fix[i];
    int old = g_sel[t];
    if (old != best) {
        atomicSub(&g_cnt[old], 1);
        atomicAdd(&g_cnt[best], 1);
        g_sel[t] = best;
    }
}

// ---------------- LayerNorm + residual epilogue (fp16 g_do) ----------------
__global__ void __launch_bounds__(256)
ln_out_kernel(const float* __restrict__ x, const float* __restrict__ ln_g,
              const float* __restrict__ ln_b, float* __restrict__ out)
{
    int r = blockIdx.x;
    int e = (r >= g_off[1]) + (r >= g_off[2]);
    int t = g_idx[r];
    const __half* row = g_do + (size_t)r * DDIM;
    int tid = threadIdx.x;
    int c = tid << 2;

    uint2 u0 = *(const uint2*)(row + c);
    uint2 u1 = *(const uint2*)(row + 1024 + c);
    float2 f00 = __half22float2(*(__half2*)&u0.x);
    float2 f01 = __half22float2(*(__half2*)&u0.y);
    float2 f10 = __half22float2(*(__half2*)&u1.x);
    float2 f11 = __half22float2(*(__half2*)&u1.y);
    float4 v0 = make_float4(f00.x, f00.y, f01.x, f01.y);
    float4 v1 = make_float4(f10.x, f10.y, f11.x, f11.y);

    float s1 = v0.x + v0.y + v0.z + v0.w + v1.x + v1.y + v1.z + v1.w;
    float s2 = v0.x * v0.x + v0.y * v0.y + v0.z * v0.z + v0.w * v0.w
             + v1.x * v1.x + v1.y * v1.y + v1.z * v1.z + v1.w * v1.w;

    __shared__ float red[8][2];
    __shared__ float stats[2];
    int lane = tid & 31, w = tid >> 5;
    #pragma unroll
    for (int o = 16; o; o >>= 1) {
        s1 += __shfl_down_sync(0xffffffffu, s1, o);
        s2 += __shfl_down_sync(0xffffffffu, s2, o);
    }
    if (lane == 0) { red[w][0] = s1; red[w][1] = s2; }
    __syncthreads();
    if (tid == 0) {
        float a1 = 0.f, a2 = 0.f;
        for (int q = 0; q < 8; q++) { a1 += red[q][0]; a2 += red[q][1]; }
        float mu = a1 * (1.f / DDIM);
        float var = a2 * (1.f / DDIM) - mu * mu;
        if (var < 0.f) var = 0.f;
        stats[0] = mu;
        stats[1] = rsqrtf(var + LN_EPS);
    }
    __syncthreads();
    float mu = stats[0], rstd = stats[1];
    float s = g_strength[t];

    const float* xr = x + (size_t)t * DDIM;
    const float* gg = ln_g + (size_t)e * DDIM;
    const float* bb = ln_b + (size_t)e * DDIM;
    float* orow = out + (size_t)t * DDIM;

    float4 xv, gv, bv, ov;
    xv = *(const float4*)(xr + c); gv = *(const float4*)(gg + c); bv = *(const float4*)(bb + c);
    ov.x = xv.x + s * ((v0.x - mu) * rstd * gv.x + bv.x);
    ov.y = xv.y + s * ((v0.y - mu) * rstd * gv.y + bv.y);
    ov.z = xv.z + s * ((v0.z - mu) * rstd * gv.z + bv.z);
    ov.w = xv.w + s * ((v0.w - mu) * rstd * gv.w + bv.w);
    *(float4*)(orow + c) = ov;
    xv = *(const float4*)(xr + 1024 + c); gv = *(const float4*)(gg + 1024 + c); bv = *(const float4*)(bb + 1024 + c);
    ov.x = xv.x + s * ((v1.x - mu) * rstd * gv.x + bv.x);
    ov.y = xv.y + s * ((v1.y - mu) * rstd * gv.y + bv.y);
    ov.z = xv.z + s * ((v1.z - mu) * rstd * gv.z + bv.z);
    ov.w = xv.w + s * ((v1.w - mu) * rstd * gv.w + bv.w);
    *(float4*)(orow + 1024 + c) = ov;
}

// ---------------- launch ----------------
extern "C" void kernel_launch(void* const* d_in, const int* in_sizes, int n_in,
                              void* d_out, int out_size)
{
    const float* x       = (const float*)d_in[0];
    const float* eps     = (const float*)d_in[1];
    const float* cls_w1  = (const float*)d_in[2];
    const float* cls_b1  = (const float*)d_in[3];
    const float* cls_w2  = (const float*)d_in[4];
    const float* cls_b2  = (const float*)d_in[5];
    const float* var_w1  = (const float*)d_in[6];
    const float* var_b1  = (const float*)d_in[7];
    const float* var_w2  = (const float*)d_in[8];
    const float* var_b2  = (const float*)d_in[9];
    const float* enc_w1  = (const float*)d_in[10];
    const float* enc_b1  = (const float*)d_in[11];
    const float* enc_w2  = (const float*)d_in[12];
    const float* enc_b2  = (const float*)d_in[13];
    const float* dec_w1  = (const float*)d_in[14];
    const float* dec_b1  = (const float*)d_in[15];
    const float* dec_w2  = (const float*)d_in[16];
    const float* dec_b2  = (const float*)d_in[17];
    const float* ln_g    = (const float*)d_in[18];
    const float* ln_b    = (const float*)d_in[19];

    float* out       = (float*)d_out;
    float* out_noise = out + (size_t)T_TOK * DDIM;
    float* out_mean  = out_noise + (size_t)T_TOK * ND;
    float* out_lv    = out_mean + (size_t)T_TOK * ND;

    cudaFuncSetAttribute(mma_gemm_kernel<0>, cudaFuncAttributeMaxDynamicSharedMemorySize, GEMM_SMEM);
    cudaFuncSetAttribute(mma_gemm_kernel<1>, cudaFuncAttributeMaxDynamicSharedMemorySize, GEMM_SMEM);
    cudaFuncSetAttribute(mma_gemm_kernel<2>, cudaFuncAttributeMaxDynamicSharedMemorySize, GEMM_SMEM);
    cudaFuncSetAttribute(enc1_kernel, cudaFuncAttributeMaxDynamicSharedMemorySize, E1_SMEM);

    split_x_kernel<<<((size_t)T_TOK * DDIM) / 2048, 256>>>(x);
    bias_fuse_kernel<<<8, 256>>>(cls_b1, var_b1);
    conv_w1t_kernel<<<dim3(64, 64), 256>>>(cls_w1, var_w1);

    // stage 1
    mma_gemm_kernel<0><<<dim3(DDIM / BN, T_TOK / BM, 1), 256, GEMM_SMEM>>>(dec_b2, dec_b1, cls_w2, var_w2);

    init_kernel<<<1, 32>>>();
    conv_w2t_kernel<<<dim3(64, 64, NE), 256>>>(dec_w2);
    conv_we1t_kernel<<<dim3(2, 64, NE), 256>>>(enc_w1);
    conv_wd1t_kernel<<<dim3(64, 2, NE), 256>>>(dec_w1);

    heads_lite_kernel<<<T_TOK / 256, 256>>>(cls_b2, var_b2);
    fixup_h_kernel<<<dim3(64, 4), 256>>>(x, cls_w1, cls_b1, cls_w2);
    fixup_sel_kernel<<<FIXCAP / 256, 256>>>(cls_b2);
    scan_kernel<<<1, 1>>>();
    scatter_kernel<<<T_TOK / 256, 256>>>();

    enc1_kernel<<<dim3(1, T_TOK / BM, NE), 256, E1_SMEM>>>(enc_b1);
    enc2_kernel<<<dim3(512, 1, NE), 256>>>(eps, enc_w2, enc_b2, out_noise, out_mean, out_lv);

    mma_gemm_kernel<2><<<dim3(DDIM / BN, T_TOK / BM, NE), 256, GEMM_SMEM>>>(dec_b2, dec_b1, cls_w2, var_w2);
    mma_gemm_kernel<1><<<dim3(DDIM / BN, T_TOK / BM, NE), 256, GEMM_SMEM>>>(dec_b2, dec_b1, cls_w2, var_w2);

    ln_out_kernel<<<T_TOK, 256>>>(x, ln_g, ln_b, out);
}